// round 13
// baseline (speedup 1.0000x reference)
#include <cuda_runtime.h>
#include <math.h>
#include <stdint.h>

#define N_ENTS 50000
#define N_RELS 500
#define NTOT   50500
#define EMB    256
#define NEDGE  400000
#define BATCH  512
#define BN_EPS 1e-5f

// ---------------- static scratch (no allocations allowed) ----------------
__device__ __align__(16) float g_XRa [(size_t)NTOT * EMB];
__device__ __align__(16) float g_XRb [(size_t)NTOT * EMB];
__device__ __align__(16) float g_S   [(size_t)NTOT * EMB];   // support buffer
__device__ __align__(16) float g_XRrf[(size_t)NTOT * EMB];   // gcn2 output
__device__ __align__(16) float g_Xef [(size_t)N_ENTS * EMB]; // gcn1 output
__device__ __align__(16) float g_hr  [BATCH * EMB];
__device__ __align__(16) float g_hrbn[BATCH * EMB];
__device__ float g_sums[EMB], g_sumsq[EMB], g_scale[EMB], g_bias[EMB];
__device__ __align__(16) float g_HG1T[EMB * EMB];
__device__ __align__(16) float g_HG2T[EMB * EMB];
__device__ __align__(16) float g_HeT [EMB * EMB];
__device__ __align__(16) float g_HrT [EMB * EMB];

// ---------------- weight prep: transposed Hamilton matrices ----------------
__global__ void build_gcn_ht(const float* __restrict__ W, float* __restrict__ HT) {
    int idx = blockIdx.x * blockDim.x + threadIdx.x;      // 256*256
    int j = idx >> 8, a = idx & 255;                      // HT[j][a] = H[a][j]
    int Bq = j >> 6, t = j & 63, Aq = a >> 6, p = a & 63;
    int comp = Aq ^ Bq;
    float s = ((0x5390 >> (Aq * 4 + Bq)) & 1) ? -1.f : 1.f;
    HT[idx] = s * W[p * 256 + comp * 64 + t];
}

__global__ void build_lin_ht(const float* __restrict__ Wl,
                             float* __restrict__ HeT, float* __restrict__ HrT) {
    int idx = blockIdx.x * blockDim.x + threadIdx.x;
    int j = idx >> 8, u = idx & 255;
    int Bq = j >> 6, t = j & 63, qe = u >> 6, w = u & 63;
    int comp = qe ^ Bq;
    float s = ((0x5390 >> (qe * 4 + Bq)) & 1) ? -1.f : 1.f;
    HeT[idx] = s * Wl[w        * 256 + comp * 64 + t];
    HrT[idx] = s * Wl[(64 + w) * 256 + comp * 64 + t];
}

// ---------------- TF32 tensor-core helpers ----------------
__device__ __forceinline__ uint32_t f32_to_tf32(float x) {
    uint32_t r;
    asm("cvt.rna.tf32.f32 %0, %1;" : "=r"(r) : "f"(x));
    return r;
}

// split x into hi (tf32) + lo (tf32 of residual): ~22 mantissa bits total
__device__ __forceinline__ void split_tf32(float x, uint32_t& h, uint32_t& l) {
    h = f32_to_tf32(x);
    l = f32_to_tf32(x - __uint_as_float(h));
}

__device__ __forceinline__ void mma_tf32(float* c, const uint32_t* a, const uint32_t* b) {
    asm volatile(
        "mma.sync.aligned.m16n8k8.row.col.f32.tf32.tf32.f32 "
        "{%0,%1,%2,%3}, {%4,%5,%6,%7}, {%8,%9}, {%0,%1,%2,%3};\n"
        : "+f"(c[0]), "+f"(c[1]), "+f"(c[2]), "+f"(c[3])
        : "r"(a[0]), "r"(a[1]), "r"(a[2]), "r"(a[3]), "r"(b[0]), "r"(b[1]));
}

// ---------------- 3xTF32 NT GEMM core (register-staged pipeline) ----------------
// C(MxN) = sum_pairs A(MxK) * B(NxK)^T, near-fp32 via hi/lo split (hh+hl+lh).
// BM=128, BN=128, BK=16, 256 threads = 8 warps (2m x 4n), warp tile 64x32.
// PAIRS: 1 = single A/B (KTOT=256), 2 = dual fused (KTOT=512, second pair after 256)
// EPI: 0 = store, 2 = sigmoid then store
template<int EPI, int PAIRS>
__global__ void __launch_bounds__(256)
gemm_tf32x3(const float* __restrict__ A1, const float* __restrict__ B1,
            const float* __restrict__ A2, const float* __restrict__ B2,
            float* __restrict__ C, int M, int N) {
    __shared__ uint32_t Ah[128][20];   // [m][k], stride 20 -> conflict-free frags
    __shared__ uint32_t Al[128][20];
    __shared__ uint32_t Bh[128][20];   // [n][k]
    __shared__ uint32_t Bl[128][20];
    const int bm = blockIdx.y * 128;
    const int bn = blockIdx.x * 128;
    const int tid = threadIdx.x;
    const int warp = tid >> 5, lane = tid & 31;
    const int wm = warp >> 2, wn = warp & 3;       // warp tile origin
    const int grp = lane >> 2, thr = lane & 3;     // mma lane decomposition
    const int KTOT = PAIRS * 256;

    // per-thread load slots: p in {0,1}: row = tid/4 + 64p, kq = (tid%4)*4
    const int lrow = tid >> 2;
    const int lkq  = (tid & 3) * 4;

    float acc[4][4][4];                            // [mtile][ntile][frag]
#pragma unroll
    for (int i = 0; i < 4; i++)
#pragma unroll
        for (int j = 0; j < 4; j++)
#pragma unroll
            for (int q = 0; q < 4; q++) acc[i][j][q] = 0.f;

    auto load_g = [&](int k0, float4* avs, float4* bvs) {
        const float* A = (PAIRS == 2 && k0 >= 256) ? A2 : A1;
        const float* B = (PAIRS == 2 && k0 >= 256) ? B2 : B1;
        int kk = k0 & 255;
#pragma unroll
        for (int p = 0; p < 2; p++) {
            int row = lrow + p * 64;
            int gr = bm + row, gc = bn + row;
            avs[p] = (gr < M) ? *(const float4*)(A + (size_t)gr * 256 + kk + lkq)
                              : make_float4(0.f, 0.f, 0.f, 0.f);
            bvs[p] = (gc < N) ? *(const float4*)(B + (size_t)gc * 256 + kk + lkq)
                              : make_float4(0.f, 0.f, 0.f, 0.f);
        }
    };
    auto sts_split = [&](float4* avs, float4* bvs) {
#pragma unroll
        for (int p = 0; p < 2; p++) {
            int row = lrow + p * 64;
            split_tf32(avs[p].x, Ah[row][lkq + 0], Al[row][lkq + 0]);
            split_tf32(avs[p].y, Ah[row][lkq + 1], Al[row][lkq + 1]);
            split_tf32(avs[p].z, Ah[row][lkq + 2], Al[row][lkq + 2]);
            split_tf32(avs[p].w, Ah[row][lkq + 3], Al[row][lkq + 3]);
            split_tf32(bvs[p].x, Bh[row][lkq + 0], Bl[row][lkq + 0]);
            split_tf32(bvs[p].y, Bh[row][lkq + 1], Bl[row][lkq + 1]);
            split_tf32(bvs[p].z, Bh[row][lkq + 2], Bl[row][lkq + 2]);
            split_tf32(bvs[p].w, Bh[row][lkq + 3], Bl[row][lkq + 3]);
        }
    };

    // prologue: stage first tile
    {
        float4 av[2], bv[2];
        load_g(0, av, bv);
        sts_split(av, bv);
    }
    __syncthreads();

    for (int k0 = 0; k0 < KTOT; k0 += 16) {
        // issue next tile's global loads early (latency hides under MMAs)
        bool more = (k0 + 16 < KTOT);
        float4 av[2], bv[2];
        if (more) load_g(k0 + 16, av, bv);

#pragma unroll
        for (int k8 = 0; k8 < 2; k8++) {
            const int kk = k8 * 8;
            uint32_t ah[4][4], al[4][4];
#pragma unroll
            for (int i = 0; i < 4; i++) {
                int m0 = wm * 64 + i * 16;
                ah[i][0] = Ah[m0 + grp    ][kk + thr    ];
                ah[i][1] = Ah[m0 + grp + 8][kk + thr    ];
                ah[i][2] = Ah[m0 + grp    ][kk + thr + 4];
                ah[i][3] = Ah[m0 + grp + 8][kk + thr + 4];
                al[i][0] = Al[m0 + grp    ][kk + thr    ];
                al[i][1] = Al[m0 + grp + 8][kk + thr    ];
                al[i][2] = Al[m0 + grp    ][kk + thr + 4];
                al[i][3] = Al[m0 + grp + 8][kk + thr + 4];
            }
            uint32_t bh[4][2], bl[4][2];
#pragma unroll
            for (int j = 0; j < 4; j++) {
                int n0 = wn * 32 + j * 8;
                bh[j][0] = Bh[n0 + grp][kk + thr    ];
                bh[j][1] = Bh[n0 + grp][kk + thr + 4];
                bl[j][0] = Bl[n0 + grp][kk + thr    ];
                bl[j][1] = Bl[n0 + grp][kk + thr + 4];
            }
#pragma unroll
            for (int i = 0; i < 4; i++)
#pragma unroll
                for (int j = 0; j < 4; j++) {
                    mma_tf32(acc[i][j], al[i], bh[j]);   // small terms first
                    mma_tf32(acc[i][j], ah[i], bl[j]);
                    mma_tf32(acc[i][j], ah[i], bh[j]);
                }
        }
        __syncthreads();                 // all warps done reading this tile
        if (more) sts_split(av, bv);     // overwrite with next tile
        __syncthreads();
    }

    // epilogue: c0 at (grp, 2*thr), c1 at (grp, 2*thr+1), c2/c3 at row+8
#pragma unroll
    for (int i = 0; i < 4; i++) {
        int mbase = bm + wm * 64 + i * 16;
#pragma unroll
        for (int j = 0; j < 4; j++) {
            int nbase = bn + wn * 32 + j * 8;
#pragma unroll
            for (int h = 0; h < 2; h++) {            // row half
                int gr = mbase + grp + h * 8;
                if (gr >= M) continue;
#pragma unroll
                for (int q = 0; q < 2; q++) {        // col pair
                    int gc = nbase + thr * 2 + q;
                    if (gc >= N) continue;
                    size_t o = (size_t)gr * N + gc;
                    float v = acc[i][j][h * 2 + q];
                    if (EPI == 2) v = 1.f / (1.f + __expf(-v));
                    C[o] = v;
                }
            }
        }
    }
}

// ---------------- segment sum: Agg[rows[e]] += vals[e] * S[cols[e]] ----------------
__global__ void segsum(const int* __restrict__ rows, const int* __restrict__ cols,
                       const float* __restrict__ vals, const float* __restrict__ S,
                       float* __restrict__ Agg, int nE) {
    int w = (blockIdx.x * blockDim.x + threadIdx.x) >> 5;
    int lane = threadIdx.x & 31;
    if (w >= nE) return;
    int r = rows[w], c = cols[w];
    float v = vals[w];
    const float4* src = (const float4*)(S + (size_t)c * EMB);
    float4* dst = (float4*)(Agg + (size_t)r * EMB);
#pragma unroll
    for (int i = 0; i < 2; i++) {
        float4 x = src[lane + 32 * i];
        x.x *= v; x.y *= v; x.z *= v; x.w *= v;
        atomicAdd(dst + lane + 32 * i, x);   // red.global.add.v4.f32 (sm_90+)
    }
}

// ---------------- batchnorm helpers ----------------
__global__ void bn_stats(const float* __restrict__ X, int rows,
                         float* __restrict__ sums, float* __restrict__ sumsq) {
    int col = threadIdx.x;                   // 256 threads
    int nb = gridDim.x;
    int per = (rows + nb - 1) / nb;
    int r0 = blockIdx.x * per;
    int r1 = min(rows, r0 + per);
    float s = 0.f, s2 = 0.f;
    for (int r = r0; r < r1; r++) {
        float v = X[(size_t)r * EMB + col];
        s += v; s2 += v * v;
    }
    atomicAdd(&sums[col], s);
    atomicAdd(&sumsq[col], s2);
}

__global__ void bn_finalize(const float* __restrict__ sums, const float* __restrict__ sumsq,
                            float n, const float* __restrict__ gamma,
                            const float* __restrict__ beta,
                            float* __restrict__ scale, float* __restrict__ bias) {
    int c = threadIdx.x;
    float m = sums[c] / n;
    float var = sumsq[c] / n - m * m;
    float sc = gamma[c] * rsqrtf(var + BN_EPS);
    scale[c] = sc;
    bias[c]  = beta[c] - m * sc;
}

template<bool TANH>
__global__ void bn_apply(const float* __restrict__ X, const float* __restrict__ scale,
                         const float* __restrict__ bias, float* __restrict__ Y, int n4) {
    int i = blockIdx.x * blockDim.x + threadIdx.x;
    if (i >= n4) return;
    float4 x = ((const float4*)X)[i];
    int c = (i & 63) * 4;                    // row stride = 64 float4
    float4 y;
    y.x = x.x * scale[c + 0] + bias[c + 0];
    y.y = x.y * scale[c + 1] + bias[c + 1];
    y.z = x.z * scale[c + 2] + bias[c + 2];
    y.w = x.w * scale[c + 3] + bias[c + 3];
    if (TANH) { y.x = tanhf(y.x); y.y = tanhf(y.y); y.z = tanhf(y.z); y.w = tanhf(y.w); }
    ((float4*)Y)[i] = y;
}

// ---------------- hr = h (x) normalize(p)  (quaternion, per 64-slot) ----------------
__global__ void hr_quat(const int* __restrict__ e1, const int* __restrict__ ridx,
                        const float* __restrict__ X, const float* __restrict__ R,
                        float* __restrict__ hr) {
    int b = blockIdx.x, t = threadIdx.x;     // 512 blocks x 64 threads
    const float* h = X + (size_t)e1[b] * EMB;
    const float* p = R + (size_t)ridx[b] * EMB;
    float pr = p[t], pi = p[64 + t], pj = p[128 + t], pk = p[192 + t];
    float inv = 1.f / sqrtf(pr * pr + pi * pi + pj * pj + pk * pk);
    pr *= inv; pi *= inv; pj *= inv; pk *= inv;
    float hrr = h[t], hi = h[64 + t], hj = h[128 + t], hk = h[192 + t];
    float* o = hr + (size_t)b * EMB;
    o[t]       = hrr * pr - hi * pi - hj * pj - hk * pk;
    o[64 + t]  = hi * pr + hrr * pi - hk * pj + hj * pk;
    o[128 + t] = hj * pr + hk * pi + hrr * pj - hi * pk;
    o[192 + t] = hk * pr - hj * pi + hi * pj + hrr * pk;
}

// ---------------- driver ----------------
extern "C" void kernel_launch(void* const* d_in, const int* in_sizes, int n_in,
                              void* d_out, int out_size) {
    const int*   e1     = (const int*)  d_in[0];
    const int*   ridx   = (const int*)  d_in[1];
    const float* emb    = (const float*)d_in[2];
    const float* gcn1_w = (const float*)d_in[3];
    const float* gcn2_w = (const float*)d_in[4];
    const float* gcn1_g = (const float*)d_in[5];
    const float* gcn1_b = (const float*)d_in[6];
    const float* gcn2_g = (const float*)d_in[7];
    const float* gcn2_b = (const float*)d_in[8];
    const float* lin    = (const float*)d_in[9];
    const float* bns_g  = (const float*)d_in[10];
    const float* bns_b  = (const float*)d_in[11];
    const int*   adj_r  = (const int*)  d_in[12];
    const int*   adj_c  = (const int*)  d_in[13];
    const float* adj_v  = (const float*)d_in[14];
    const int*   adjr_r = (const int*)  d_in[15];
    const int*   adjr_c = (const int*)  d_in[16];
    const float* adjr_v = (const float*)d_in[17];
    float* out = (float*)d_out;

    float *XRa, *XRb, *S, *XRrf, *Xef, *hr, *hrbn, *sums, *sumsq, *scale, *bias;
    float *HG1T, *HG2T, *HeT, *HrT;
    cudaGetSymbolAddress((void**)&XRa,   g_XRa);
    cudaGetSymbolAddress((void**)&XRb,   g_XRb);
    cudaGetSymbolAddress((void**)&S,     g_S);
    cudaGetSymbolAddress((void**)&XRrf,  g_XRrf);
    cudaGetSymbolAddress((void**)&Xef,   g_Xef);
    cudaGetSymbolAddress((void**)&hr,    g_hr);
    cudaGetSymbolAddress((void**)&hrbn,  g_hrbn);
    cudaGetSymbolAddress((void**)&sums,  g_sums);
    cudaGetSymbolAddress((void**)&sumsq, g_sumsq);
    cudaGetSymbolAddress((void**)&scale, g_scale);
    cudaGetSymbolAddress((void**)&bias,  g_bias);
    cudaGetSymbolAddress((void**)&HG1T,  g_HG1T);
    cudaGetSymbolAddress((void**)&HG2T,  g_HG2T);
    cudaGetSymbolAddress((void**)&HeT,   g_HeT);
    cudaGetSymbolAddress((void**)&HrT,   g_HrT);

    auto bn_prep = [&](const float* X, int rows, const float* gamma, const float* beta) {
        cudaMemsetAsync(sums, 0, EMB * sizeof(float));
        cudaMemsetAsync(sumsq, 0, EMB * sizeof(float));
        int grid = rows > 4096 ? 512 : 8;
        bn_stats<<<grid, 256>>>(X, rows, sums, sumsq);
        bn_finalize<<<1, 256>>>(sums, sumsq, (float)rows, gamma, beta, scale, bias);
    };

    auto score = [&](int s, const float* X, const float* R) {
        hr_quat<<<BATCH, 64>>>(e1, ridx, X, R, hr);
        bn_prep(hr, BATCH, bns_g + s * EMB, bns_b + s * EMB);
        int n4 = BATCH * EMB / 4;
        bn_apply<false><<<(n4 + 255) / 256, 256>>>(hr, scale, bias, hrbn, n4);
        dim3 g((N_ENTS + 127) / 128, (BATCH + 127) / 128);
        gemm_tf32x3<2, 1><<<g, 256>>>(hrbn, X, nullptr, nullptr,
                                      out + (size_t)s * BATCH * N_ENTS,
                                      BATCH, N_ENTS);
    };

    auto q4gnn = [&](const float* Ain, int nrows, const int* er, const int* ec,
                     const float* ev, const float* HT, const float* gamma,
                     const float* beta, float* Aout) {
        dim3 g(2, (nrows + 127) / 128);
        gemm_tf32x3<0, 1><<<g, 256>>>(Ain, HT, nullptr, nullptr, S, nrows, EMB);
        cudaMemsetAsync(Aout, 0, (size_t)nrows * EMB * sizeof(float));
        segsum<<<NEDGE / 8, 256>>>(er, ec, ev, S, Aout, NEDGE);
        bn_prep(Aout, nrows, gamma, beta);
        int n4 = nrows * EMB / 4;
        bn_apply<true><<<(n4 + 255) / 256, 256>>>(Aout, scale, bias, Aout, n4);
    };

    // score 0 on raw embeddings (X = emb[:50000], R = emb[50000:] contiguous)
    score(0, emb, emb + (size_t)N_ENTS * EMB);

    const float* XRcur = emb;
    float* XRbufs[2] = {XRa, XRb};
    for (int l = 0; l < 2; l++) {
        build_gcn_ht<<<256, 256>>>(gcn2_w + (size_t)l * 64 * 256, HG2T);
        build_gcn_ht<<<256, 256>>>(gcn1_w + (size_t)l * 64 * 256, HG1T);
        build_lin_ht<<<256, 256>>>(lin + (size_t)l * 128 * 256, HeT, HrT);

        q4gnn(XRcur, NTOT,   adjr_r, adjr_c, adjr_v, HG2T,
              gcn2_g + l * EMB, gcn2_b + l * EMB, XRrf);
        q4gnn(XRcur, N_ENTS, adj_r,  adj_c,  adj_v,  HG1T,
              gcn1_g + l * EMB, gcn1_b + l * EMB, Xef);

        // fused lin: Xnext = Xef*HeT^T + XRrf*HrT^T  (single kernel, K=512)
        float* XRnext = XRbufs[l];
        dim3 g(2, (N_ENTS + 127) / 128);
        gemm_tf32x3<0, 2><<<g, 256>>>(Xef, HeT, XRrf, HrT, XRnext, N_ENTS, EMB);
        cudaMemcpyAsync(XRnext + (size_t)N_ENTS * EMB, XRrf + (size_t)N_ENTS * EMB,
                        (size_t)N_RELS * EMB * sizeof(float), cudaMemcpyDeviceToDevice);

        score(l + 1, XRnext, XRnext + (size_t)N_ENTS * EMB);
        XRcur = XRnext;
    }
}

// round 16
// speedup vs baseline: 1.1959x; 1.1959x over previous
#include <cuda_runtime.h>
#include <math.h>
#include <stdint.h>

#define N_ENTS 50000
#define N_RELS 500
#define NTOT   50500
#define EMB    256
#define NEDGE  400000
#define BATCH  512
#define BN_EPS 1e-5f

// ---------------- static scratch (no allocations allowed) ----------------
__device__ __align__(16) float g_XRa [(size_t)NTOT * EMB];
__device__ __align__(16) float g_XRb [(size_t)NTOT * EMB];
__device__ __align__(16) float g_S   [(size_t)NTOT * EMB];   // support buffer
__device__ __align__(16) float g_XRrf[(size_t)NTOT * EMB];   // gcn2 output
__device__ __align__(16) float g_Xef [(size_t)N_ENTS * EMB]; // gcn1 output
__device__ __align__(16) float g_hr  [BATCH * EMB];
__device__ __align__(16) float g_hrbn[BATCH * EMB];
__device__ float g_sums[EMB], g_sumsq[EMB], g_scale[EMB], g_bias[EMB];
__device__ __align__(16) float g_HG1T[EMB * EMB];
__device__ __align__(16) float g_HG2T[EMB * EMB];
__device__ __align__(16) float g_HeT [EMB * EMB];
__device__ __align__(16) float g_HrT [EMB * EMB];

// ---------------- weight prep: transposed Hamilton matrices ----------------
__global__ void build_gcn_ht(const float* __restrict__ W, float* __restrict__ HT) {
    int idx = blockIdx.x * blockDim.x + threadIdx.x;      // 256*256
    int j = idx >> 8, a = idx & 255;                      // HT[j][a] = H[a][j]
    int Bq = j >> 6, t = j & 63, Aq = a >> 6, p = a & 63;
    int comp = Aq ^ Bq;
    float s = ((0x5390 >> (Aq * 4 + Bq)) & 1) ? -1.f : 1.f;
    HT[idx] = s * W[p * 256 + comp * 64 + t];
}

__global__ void build_lin_ht(const float* __restrict__ Wl,
                             float* __restrict__ HeT, float* __restrict__ HrT) {
    int idx = blockIdx.x * blockDim.x + threadIdx.x;
    int j = idx >> 8, u = idx & 255;
    int Bq = j >> 6, t = j & 63, qe = u >> 6, w = u & 63;
    int comp = qe ^ Bq;
    float s = ((0x5390 >> (qe * 4 + Bq)) & 1) ? -1.f : 1.f;
    HeT[idx] = s * Wl[w        * 256 + comp * 64 + t];
    HrT[idx] = s * Wl[(64 + w) * 256 + comp * 64 + t];
}

// ---------------- TF32 tensor-core helpers ----------------
__device__ __forceinline__ uint32_t f32_to_tf32(float x) {
    uint32_t r;
    asm("cvt.rna.tf32.f32 %0, %1;" : "=r"(r) : "f"(x));
    return r;
}

// split x into hi (tf32) + lo (tf32 of residual): ~22 mantissa bits total
__device__ __forceinline__ void split_tf32(float x, uint32_t& h, uint32_t& l) {
    h = f32_to_tf32(x);
    l = f32_to_tf32(x - __uint_as_float(h));
}

__device__ __forceinline__ void mma_tf32(float* c, const uint32_t* a, const uint32_t* b) {
    asm volatile(
        "mma.sync.aligned.m16n8k8.row.col.f32.tf32.tf32.f32 "
        "{%0,%1,%2,%3}, {%4,%5,%6,%7}, {%8,%9}, {%0,%1,%2,%3};\n"
        : "+f"(c[0]), "+f"(c[1]), "+f"(c[2]), "+f"(c[3])
        : "r"(a[0]), "r"(a[1]), "r"(a[2]), "r"(a[3]), "r"(b[0]), "r"(b[1]));
}

// ---------------- 3xTF32 NT GEMM: C(MxN) = sum_pairs A(Mx256) * B(Nx256)^T ----
// near-fp32 accuracy: A,B split hi/lo, products hh + hl + lh accumulated fp32.
// BM=128, BN=128, BK=16, 256 threads = 8 warps (2m x 4n), warp tile 64x32.
// __launch_bounds__(256,2): cap regs at 128 so TWO blocks co-reside per SM —
// one block's MMA phase hides the other's LDG/sync stalls.
// PAIRS: 1 = single A/B (K=256), 2 = fused dual source (K=512)
// EPI: 0 = store, 2 = sigmoid then store
template<int EPI, int PAIRS>
__global__ void __launch_bounds__(256, 2)
gemm_tf32x3(const float* __restrict__ A1, const float* __restrict__ B1,
            const float* __restrict__ A2, const float* __restrict__ B2,
            float* __restrict__ C, int M, int N) {
    __shared__ uint32_t Ah[128][20];   // [m][k], stride 20 -> conflict-free frags
    __shared__ uint32_t Al[128][20];
    __shared__ uint32_t Bh[128][20];   // [n][k]
    __shared__ uint32_t Bl[128][20];
    const int bm = blockIdx.y * 128;
    const int bn = blockIdx.x * 128;
    const int tid = threadIdx.x;
    const int warp = tid >> 5, lane = tid & 31;
    const int wm = warp >> 2, wn = warp & 3;       // warp tile origin
    const int grp = lane >> 2, thr = lane & 3;     // mma lane decomposition
    const int KTOT = PAIRS * 256;

    float acc[4][4][4];                            // [mtile][ntile][frag]
#pragma unroll
    for (int i = 0; i < 4; i++)
#pragma unroll
        for (int j = 0; j < 4; j++)
#pragma unroll
            for (int q = 0; q < 4; q++) acc[i][j][q] = 0.f;

    for (int k0 = 0; k0 < KTOT; k0 += 16) {
        const float* A = (PAIRS == 2 && k0 >= 256) ? A2 : A1;
        const float* B = (PAIRS == 2 && k0 >= 256) ? B2 : B1;
        const int kk0 = k0 & 255;
        __syncthreads();
        // 128 rows x 16 k = 512 float4 per matrix / 256 threads = 2 each
#pragma unroll
        for (int p = 0; p < 2; p++) {
            int f   = tid + p * 256;               // 0..511
            int row = f >> 2;
            int kq  = (f & 3) * 4;
            float4 av = make_float4(0.f, 0.f, 0.f, 0.f);
            int gr = bm + row;
            if (gr < M) av = *(const float4*)(A + (size_t)gr * 256 + kk0 + kq);
            split_tf32(av.x, Ah[row][kq + 0], Al[row][kq + 0]);
            split_tf32(av.y, Ah[row][kq + 1], Al[row][kq + 1]);
            split_tf32(av.z, Ah[row][kq + 2], Al[row][kq + 2]);
            split_tf32(av.w, Ah[row][kq + 3], Al[row][kq + 3]);
            float4 bv = make_float4(0.f, 0.f, 0.f, 0.f);
            int gc = bn + row;
            if (gc < N) bv = *(const float4*)(B + (size_t)gc * 256 + kk0 + kq);
            split_tf32(bv.x, Bh[row][kq + 0], Bl[row][kq + 0]);
            split_tf32(bv.y, Bh[row][kq + 1], Bl[row][kq + 1]);
            split_tf32(bv.z, Bh[row][kq + 2], Bl[row][kq + 2]);
            split_tf32(bv.w, Bh[row][kq + 3], Bl[row][kq + 3]);
        }
        __syncthreads();
#pragma unroll
        for (int k8 = 0; k8 < 2; k8++) {
            const int kk = k8 * 8;
            uint32_t ah[4][4], al[4][4];
#pragma unroll
            for (int i = 0; i < 4; i++) {
                int m0 = wm * 64 + i * 16;
                ah[i][0] = Ah[m0 + grp    ][kk + thr    ];
                ah[i][1] = Ah[m0 + grp + 8][kk + thr    ];
                ah[i][2] = Ah[m0 + grp    ][kk + thr + 4];
                ah[i][3] = Ah[m0 + grp + 8][kk + thr + 4];
                al[i][0] = Al[m0 + grp    ][kk + thr    ];
                al[i][1] = Al[m0 + grp + 8][kk + thr    ];
                al[i][2] = Al[m0 + grp    ][kk + thr + 4];
                al[i][3] = Al[m0 + grp + 8][kk + thr + 4];
            }
            uint32_t bh[4][2], bl[4][2];
#pragma unroll
            for (int j = 0; j < 4; j++) {
                int n0 = wn * 32 + j * 8;
                bh[j][0] = Bh[n0 + grp][kk + thr    ];
                bh[j][1] = Bh[n0 + grp][kk + thr + 4];
                bl[j][0] = Bl[n0 + grp][kk + thr    ];
                bl[j][1] = Bl[n0 + grp][kk + thr + 4];
            }
#pragma unroll
            for (int i = 0; i < 4; i++)
#pragma unroll
                for (int j = 0; j < 4; j++) {
                    mma_tf32(acc[i][j], al[i], bh[j]);   // small terms first
                    mma_tf32(acc[i][j], ah[i], bl[j]);
                    mma_tf32(acc[i][j], ah[i], bh[j]);
                }
        }
    }

    // epilogue: c0 at (grp, 2*thr), c1 at (grp, 2*thr+1), c2/c3 at row+8
#pragma unroll
    for (int i = 0; i < 4; i++) {
        int mbase = bm + wm * 64 + i * 16;
#pragma unroll
        for (int j = 0; j < 4; j++) {
            int nbase = bn + wn * 32 + j * 8;
#pragma unroll
            for (int h = 0; h < 2; h++) {            // row half
                int gr = mbase + grp + h * 8;
                if (gr >= M) continue;
#pragma unroll
                for (int q = 0; q < 2; q++) {        // col pair
                    int gc = nbase + thr * 2 + q;
                    if (gc >= N) continue;
                    size_t o = (size_t)gr * N + gc;
                    float v = acc[i][j][h * 2 + q];
                    if (EPI == 2) v = 1.f / (1.f + __expf(-v));
                    C[o] = v;
                }
            }
        }
    }
}

// ---------------- segment sum: Agg[rows[e]] += vals[e] * S[cols[e]] ----------------
__global__ void segsum(const int* __restrict__ rows, const int* __restrict__ cols,
                       const float* __restrict__ vals, const float* __restrict__ S,
                       float* __restrict__ Agg, int nE) {
    int w = (blockIdx.x * blockDim.x + threadIdx.x) >> 5;
    int lane = threadIdx.x & 31;
    if (w >= nE) return;
    int r = rows[w], c = cols[w];
    float v = vals[w];
    const float4* src = (const float4*)(S + (size_t)c * EMB);
    float4* dst = (float4*)(Agg + (size_t)r * EMB);
#pragma unroll
    for (int i = 0; i < 2; i++) {
        float4 x = src[lane + 32 * i];
        x.x *= v; x.y *= v; x.z *= v; x.w *= v;
        atomicAdd(dst + lane + 32 * i, x);   // red.global.add.v4.f32 (sm_90+)
    }
}

// ---------------- batchnorm helpers ----------------
__global__ void bn_stats(const float* __restrict__ X, int rows,
                         float* __restrict__ sums, float* __restrict__ sumsq) {
    int col = threadIdx.x;                   // 256 threads
    int nb = gridDim.x;
    int per = (rows + nb - 1) / nb;
    int r0 = blockIdx.x * per;
    int r1 = min(rows, r0 + per);
    float s = 0.f, s2 = 0.f;
    for (int r = r0; r < r1; r++) {
        float v = X[(size_t)r * EMB + col];
        s += v; s2 += v * v;
    }
    atomicAdd(&sums[col], s);
    atomicAdd(&sumsq[col], s2);
}

__global__ void bn_finalize(const float* __restrict__ sums, const float* __restrict__ sumsq,
                            float n, const float* __restrict__ gamma,
                            const float* __restrict__ beta,
                            float* __restrict__ scale, float* __restrict__ bias) {
    int c = threadIdx.x;
    float m = sums[c] / n;
    float var = sumsq[c] / n - m * m;
    float sc = gamma[c] * rsqrtf(var + BN_EPS);
    scale[c] = sc;
    bias[c]  = beta[c] - m * sc;
}

template<bool TANH>
__global__ void bn_apply(const float* __restrict__ X, const float* __restrict__ scale,
                         const float* __restrict__ bias, float* __restrict__ Y, int n4) {
    int i = blockIdx.x * blockDim.x + threadIdx.x;
    if (i >= n4) return;
    float4 x = ((const float4*)X)[i];
    int c = (i & 63) * 4;                    // row stride = 64 float4
    float4 y;
    y.x = x.x * scale[c + 0] + bias[c + 0];
    y.y = x.y * scale[c + 1] + bias[c + 1];
    y.z = x.z * scale[c + 2] + bias[c + 2];
    y.w = x.w * scale[c + 3] + bias[c + 3];
    if (TANH) { y.x = tanhf(y.x); y.y = tanhf(y.y); y.z = tanhf(y.z); y.w = tanhf(y.w); }
    ((float4*)Y)[i] = y;
}

// ---------------- hr = h (x) normalize(p)  (quaternion, per 64-slot) ----------------
__global__ void hr_quat(const int* __restrict__ e1, const int* __restrict__ ridx,
                        const float* __restrict__ X, const float* __restrict__ R,
                        float* __restrict__ hr) {
    int b = blockIdx.x, t = threadIdx.x;     // 512 blocks x 64 threads
    const float* h = X + (size_t)e1[b] * EMB;
    const float* p = R + (size_t)ridx[b] * EMB;
    float pr = p[t], pi = p[64 + t], pj = p[128 + t], pk = p[192 + t];
    float inv = 1.f / sqrtf(pr * pr + pi * pi + pj * pj + pk * pk);
    pr *= inv; pi *= inv; pj *= inv; pk *= inv;
    float hrr = h[t], hi = h[64 + t], hj = h[128 + t], hk = h[192 + t];
    float* o = hr + (size_t)b * EMB;
    o[t]       = hrr * pr - hi * pi - hj * pj - hk * pk;
    o[64 + t]  = hi * pr + hrr * pi - hk * pj + hj * pk;
    o[128 + t] = hj * pr + hk * pi + hrr * pj - hi * pk;
    o[192 + t] = hk * pr - hj * pi + hi * pj + hrr * pk;
}

// ---------------- driver ----------------
extern "C" void kernel_launch(void* const* d_in, const int* in_sizes, int n_in,
                              void* d_out, int out_size) {
    const int*   e1     = (const int*)  d_in[0];
    const int*   ridx   = (const int*)  d_in[1];
    const float* emb    = (const float*)d_in[2];
    const float* gcn1_w = (const float*)d_in[3];
    const float* gcn2_w = (const float*)d_in[4];
    const float* gcn1_g = (const float*)d_in[5];
    const float* gcn1_b = (const float*)d_in[6];
    const float* gcn2_g = (const float*)d_in[7];
    const float* gcn2_b = (const float*)d_in[8];
    const float* lin    = (const float*)d_in[9];
    const float* bns_g  = (const float*)d_in[10];
    const float* bns_b  = (const float*)d_in[11];
    const int*   adj_r  = (const int*)  d_in[12];
    const int*   adj_c  = (const int*)  d_in[13];
    const float* adj_v  = (const float*)d_in[14];
    const int*   adjr_r = (const int*)  d_in[15];
    const int*   adjr_c = (const int*)  d_in[16];
    const float* adjr_v = (const float*)d_in[17];
    float* out = (float*)d_out;

    float *XRa, *XRb, *S, *XRrf, *Xef, *hr, *hrbn, *sums, *sumsq, *scale, *bias;
    float *HG1T, *HG2T, *HeT, *HrT;
    cudaGetSymbolAddress((void**)&XRa,   g_XRa);
    cudaGetSymbolAddress((void**)&XRb,   g_XRb);
    cudaGetSymbolAddress((void**)&S,     g_S);
    cudaGetSymbolAddress((void**)&XRrf,  g_XRrf);
    cudaGetSymbolAddress((void**)&Xef,   g_Xef);
    cudaGetSymbolAddress((void**)&hr,    g_hr);
    cudaGetSymbolAddress((void**)&hrbn,  g_hrbn);
    cudaGetSymbolAddress((void**)&sums,  g_sums);
    cudaGetSymbolAddress((void**)&sumsq, g_sumsq);
    cudaGetSymbolAddress((void**)&scale, g_scale);
    cudaGetSymbolAddress((void**)&bias,  g_bias);
    cudaGetSymbolAddress((void**)&HG1T,  g_HG1T);
    cudaGetSymbolAddress((void**)&HG2T,  g_HG2T);
    cudaGetSymbolAddress((void**)&HeT,   g_HeT);
    cudaGetSymbolAddress((void**)&HrT,   g_HrT);

    auto bn_prep = [&](const float* X, int rows, const float* gamma, const float* beta) {
        cudaMemsetAsync(sums, 0, EMB * sizeof(float));
        cudaMemsetAsync(sumsq, 0, EMB * sizeof(float));
        int grid = rows > 4096 ? 512 : 8;
        bn_stats<<<grid, 256>>>(X, rows, sums, sumsq);
        bn_finalize<<<1, 256>>>(sums, sumsq, (float)rows, gamma, beta, scale, bias);
    };

    auto score = [&](int s, const float* X, const float* R) {
        hr_quat<<<BATCH, 64>>>(e1, ridx, X, R, hr);
        bn_prep(hr, BATCH, bns_g + s * EMB, bns_b + s * EMB);
        int n4 = BATCH * EMB / 4;
        bn_apply<false><<<(n4 + 255) / 256, 256>>>(hr, scale, bias, hrbn, n4);
        dim3 g((N_ENTS + 127) / 128, (BATCH + 127) / 128);
        gemm_tf32x3<2, 1><<<g, 256>>>(hrbn, X, nullptr, nullptr,
                                      out + (size_t)s * BATCH * N_ENTS,
                                      BATCH, N_ENTS);
    };

    auto q4gnn = [&](const float* Ain, int nrows, const int* er, const int* ec,
                     const float* ev, const float* HT, const float* gamma,
                     const float* beta, float* Aout) {
        dim3 g(2, (nrows + 127) / 128);
        gemm_tf32x3<0, 1><<<g, 256>>>(Ain, HT, nullptr, nullptr, S, nrows, EMB);
        cudaMemsetAsync(Aout, 0, (size_t)nrows * EMB * sizeof(float));
        segsum<<<NEDGE / 8, 256>>>(er, ec, ev, S, Aout, NEDGE);
        bn_prep(Aout, nrows, gamma, beta);
        int n4 = nrows * EMB / 4;
        bn_apply<true><<<(n4 + 255) / 256, 256>>>(Aout, scale, bias, Aout, n4);
    };

    // score 0 on raw embeddings (X = emb[:50000], R = emb[50000:] contiguous)
    score(0, emb, emb + (size_t)N_ENTS * EMB);

    const float* XRcur = emb;
    float* XRbufs[2] = {XRa, XRb};
    for (int l = 0; l < 2; l++) {
        build_gcn_ht<<<256, 256>>>(gcn2_w + (size_t)l * 64 * 256, HG2T);
        build_gcn_ht<<<256, 256>>>(gcn1_w + (size_t)l * 64 * 256, HG1T);
        build_lin_ht<<<256, 256>>>(lin + (size_t)l * 128 * 256, HeT, HrT);

        q4gnn(XRcur, NTOT,   adjr_r, adjr_c, adjr_v, HG2T,
              gcn2_g + l * EMB, gcn2_b + l * EMB, XRrf);
        q4gnn(XRcur, N_ENTS, adj_r,  adj_c,  adj_v,  HG1T,
              gcn1_g + l * EMB, gcn1_b + l * EMB, Xef);

        // fused lin: Xnext = Xef*HeT^T + XRrf*HrT^T  (single kernel, K=512)
        float* XRnext = XRbufs[l];
        dim3 g(2, (N_ENTS + 127) / 128);
        gemm_tf32x3<0, 2><<<g, 256>>>(Xef, HeT, XRrf, HrT, XRnext, N_ENTS, EMB);
        cudaMemcpyAsync(XRnext + (size_t)N_ENTS * EMB, XRrf + (size_t)N_ENTS * EMB,
                        (size_t)N_RELS * EMB * sizeof(float), cudaMemcpyDeviceToDevice);

        score(l + 1, XRnext, XRnext + (size_t)N_ENTS * EMB);
        XRcur = XRnext;
    }
}

// round 17
// speedup vs baseline: 1.3625x; 1.1393x over previous
#include <cuda_runtime.h>
#include <math.h>
#include <stdint.h>

#define N_ENTS 50000
#define N_RELS 500
#define NTOT   50500
#define EMB    256
#define NEDGE  400000
#define BATCH  512
#define BN_EPS 1e-5f

// ---------------- static scratch (no allocations allowed) ----------------
__device__ __align__(16) float g_XRa [(size_t)NTOT * EMB];
__device__ __align__(16) float g_XRb [(size_t)NTOT * EMB];
__device__ __align__(16) float g_S   [(size_t)NTOT * EMB];   // support buffer
__device__ __align__(16) float g_XRrf[(size_t)NTOT * EMB];   // gcn2 output
__device__ __align__(16) float g_Xef [(size_t)N_ENTS * EMB]; // gcn1 output
__device__ __align__(16) float g_hr  [BATCH * EMB];
__device__ __align__(16) float g_hrbn[BATCH * EMB];
__device__ float g_sums[EMB], g_sumsq[EMB], g_scale[EMB], g_bias[EMB];
__device__ __align__(16) float g_HG1T[EMB * EMB];
__device__ __align__(16) float g_HG2T[EMB * EMB];
__device__ __align__(16) float g_HeT [EMB * EMB];
__device__ __align__(16) float g_HrT [EMB * EMB];

// ---------------- weight prep: transposed Hamilton matrices ----------------
__global__ void build_gcn_ht(const float* __restrict__ W, float* __restrict__ HT) {
    int idx = blockIdx.x * blockDim.x + threadIdx.x;      // 256*256
    int j = idx >> 8, a = idx & 255;                      // HT[j][a] = H[a][j]
    int Bq = j >> 6, t = j & 63, Aq = a >> 6, p = a & 63;
    int comp = Aq ^ Bq;
    float s = ((0x5390 >> (Aq * 4 + Bq)) & 1) ? -1.f : 1.f;
    HT[idx] = s * W[p * 256 + comp * 64 + t];
}

__global__ void build_lin_ht(const float* __restrict__ Wl,
                             float* __restrict__ HeT, float* __restrict__ HrT) {
    int idx = blockIdx.x * blockDim.x + threadIdx.x;
    int j = idx >> 8, u = idx & 255;
    int Bq = j >> 6, t = j & 63, qe = u >> 6, w = u & 63;
    int comp = qe ^ Bq;
    float s = ((0x5390 >> (qe * 4 + Bq)) & 1) ? -1.f : 1.f;
    HeT[idx] = s * Wl[w        * 256 + comp * 64 + t];
    HrT[idx] = s * Wl[(64 + w) * 256 + comp * 64 + t];
}

// ---------------- TF32 tensor-core helpers ----------------
__device__ __forceinline__ uint32_t f32_to_tf32(float x) {
    uint32_t r;
    asm("cvt.rna.tf32.f32 %0, %1;" : "=r"(r) : "f"(x));
    return r;
}

// split x into hi (tf32) + lo (tf32 of residual): ~22 mantissa bits total
__device__ __forceinline__ void split_tf32(float x, uint32_t& h, uint32_t& l) {
    h = f32_to_tf32(x);
    l = f32_to_tf32(x - __uint_as_float(h));
}

__device__ __forceinline__ void mma_tf32(float* c, const uint32_t* a, const uint32_t* b) {
    asm volatile(
        "mma.sync.aligned.m16n8k8.row.col.f32.tf32.tf32.f32 "
        "{%0,%1,%2,%3}, {%4,%5,%6,%7}, {%8,%9}, {%0,%1,%2,%3};\n"
        : "+f"(c[0]), "+f"(c[1]), "+f"(c[2]), "+f"(c[3])
        : "r"(a[0]), "r"(a[1]), "r"(a[2]), "r"(a[3]), "r"(b[0]), "r"(b[1]));
}

// ---------------- 3xTF32 NT GEMM: C(MxN) = sum_pairs A(Mx256) * B(Nx256)^T ----
// cp.async double-buffered: raw fp32 tiles in smem (half the footprint/traffic),
// hi/lo split done in registers at fragment-load time. No staging registers —
// global-load latency hides under the previous tile's MMA phase.
// BM=128, BN=128, BK=16, 256 threads = 8 warps (2m x 4n), warp tile 64x32.
// PAIRS: 1 = single A/B (K=256), 2 = fused dual source (K=512)
// EPI: 0 = store, 2 = sigmoid then store
template<int EPI, int PAIRS>
__global__ void __launch_bounds__(256, 2)
gemm_tf32x3(const float* __restrict__ A1, const float* __restrict__ B1,
            const float* __restrict__ A2, const float* __restrict__ B2,
            float* __restrict__ C, int M, int N) {
    __shared__ float As[2][128][20];   // raw fp32, stride 20 -> conflict-free frags
    __shared__ float Bs[2][128][20];
    const int bm = blockIdx.y * 128;
    const int bn = blockIdx.x * 128;
    const int tid = threadIdx.x;
    const int warp = tid >> 5, lane = tid & 31;
    const int wm = warp >> 2, wn = warp & 3;       // warp tile origin
    const int grp = lane >> 2, thr = lane & 3;     // mma lane decomposition
    const int NT = PAIRS * 16;                     // number of BK=16 k-tiles

    // per-thread cp.async slots: 2 rows x one 16B chunk per matrix per slot
    const int crow = tid >> 2;                     // 0..63 (p=0), +64 (p=1)
    const int ccol = (tid & 3) * 4;                // word offset 0,4,8,12

    float acc[4][4][4];                            // [mtile][ntile][frag]
#pragma unroll
    for (int i = 0; i < 4; i++)
#pragma unroll
        for (int j = 0; j < 4; j++)
#pragma unroll
            for (int q = 0; q < 4; q++) acc[i][j][q] = 0.f;

    auto issue_tile = [&](int t, int stage) {
        const float* A = (PAIRS == 2 && t >= 16) ? A2 : A1;
        const float* B = (PAIRS == 2 && t >= 16) ? B2 : B1;
        int kk = (t * 16) & 255;
#pragma unroll
        for (int p = 0; p < 2; p++) {
            int row = crow + p * 64;
            int gr = bm + row, gc = bn + row;
            int pa = (gr < M) ? 16 : 0;
            int pb = (gc < N) ? 16 : 0;
            int grc = gr < M ? gr : M - 1;         // clamp: address always valid
            int gcc = gc < N ? gc : N - 1;
            uint32_t sa = (uint32_t)__cvta_generic_to_shared(&As[stage][row][ccol]);
            uint32_t sb = (uint32_t)__cvta_generic_to_shared(&Bs[stage][row][ccol]);
            const float* ga = A + (size_t)grc * 256 + kk + ccol;
            const float* gb = B + (size_t)gcc * 256 + kk + ccol;
            asm volatile("cp.async.cg.shared.global [%0], [%1], 16, %2;"
                         :: "r"(sa), "l"(ga), "r"(pa));
            asm volatile("cp.async.cg.shared.global [%0], [%1], 16, %2;"
                         :: "r"(sb), "l"(gb), "r"(pb));
        }
        asm volatile("cp.async.commit_group;");
    };

    issue_tile(0, 0);

    for (int t = 0; t < NT; t++) {
        const int st = t & 1;
        if (t + 1 < NT) {
            issue_tile(t + 1, st ^ 1);
            asm volatile("cp.async.wait_group 1;");   // tile t resident
        } else {
            asm volatile("cp.async.wait_group 0;");
        }
        __syncthreads();

#pragma unroll
        for (int k8 = 0; k8 < 2; k8++) {
            const int kk = k8 * 8;
            uint32_t ah[4][4], al[4][4];
#pragma unroll
            for (int i = 0; i < 4; i++) {
                int m0 = wm * 64 + i * 16;
                split_tf32(As[st][m0 + grp    ][kk + thr    ], ah[i][0], al[i][0]);
                split_tf32(As[st][m0 + grp + 8][kk + thr    ], ah[i][1], al[i][1]);
                split_tf32(As[st][m0 + grp    ][kk + thr + 4], ah[i][2], al[i][2]);
                split_tf32(As[st][m0 + grp + 8][kk + thr + 4], ah[i][3], al[i][3]);
            }
            uint32_t bh[4][2], bl[4][2];
#pragma unroll
            for (int j = 0; j < 4; j++) {
                int n0 = wn * 32 + j * 8;
                split_tf32(Bs[st][n0 + grp][kk + thr    ], bh[j][0], bl[j][0]);
                split_tf32(Bs[st][n0 + grp][kk + thr + 4], bh[j][1], bl[j][1]);
            }
#pragma unroll
            for (int i = 0; i < 4; i++)
#pragma unroll
                for (int j = 0; j < 4; j++) {
                    mma_tf32(acc[i][j], al[i], bh[j]);   // small terms first
                    mma_tf32(acc[i][j], ah[i], bl[j]);
                    mma_tf32(acc[i][j], ah[i], bh[j]);
                }
        }
        __syncthreads();    // all reads of stage st done before it is refilled
    }

    // epilogue: c0 at (grp, 2*thr), c1 at (grp, 2*thr+1), c2/c3 at row+8
#pragma unroll
    for (int i = 0; i < 4; i++) {
        int mbase = bm + wm * 64 + i * 16;
#pragma unroll
        for (int j = 0; j < 4; j++) {
            int nbase = bn + wn * 32 + j * 8;
#pragma unroll
            for (int h = 0; h < 2; h++) {            // row half
                int gr = mbase + grp + h * 8;
                if (gr >= M) continue;
#pragma unroll
                for (int q = 0; q < 2; q++) {        // col pair
                    int gc = nbase + thr * 2 + q;
                    if (gc >= N) continue;
                    size_t o = (size_t)gr * N + gc;
                    float v = acc[i][j][h * 2 + q];
                    if (EPI == 2) v = 1.f / (1.f + __expf(-v));
                    C[o] = v;
                }
            }
        }
    }
}

// ---------------- segment sum: Agg[rows[e]] += vals[e] * S[cols[e]] ----------------
__global__ void segsum(const int* __restrict__ rows, const int* __restrict__ cols,
                       const float* __restrict__ vals, const float* __restrict__ S,
                       float* __restrict__ Agg, int nE) {
    int w = (blockIdx.x * blockDim.x + threadIdx.x) >> 5;
    int lane = threadIdx.x & 31;
    if (w >= nE) return;
    int r = rows[w], c = cols[w];
    float v = vals[w];
    const float4* src = (const float4*)(S + (size_t)c * EMB);
    float4* dst = (float4*)(Agg + (size_t)r * EMB);
#pragma unroll
    for (int i = 0; i < 2; i++) {
        float4 x = src[lane + 32 * i];
        x.x *= v; x.y *= v; x.z *= v; x.w *= v;
        atomicAdd(dst + lane + 32 * i, x);   // red.global.add.v4.f32 (sm_90+)
    }
}

// ---------------- batchnorm helpers ----------------
__global__ void bn_stats(const float* __restrict__ X, int rows,
                         float* __restrict__ sums, float* __restrict__ sumsq) {
    int col = threadIdx.x;                   // 256 threads
    int nb = gridDim.x;
    int per = (rows + nb - 1) / nb;
    int r0 = blockIdx.x * per;
    int r1 = min(rows, r0 + per);
    float s = 0.f, s2 = 0.f;
    for (int r = r0; r < r1; r++) {
        float v = X[(size_t)r * EMB + col];
        s += v; s2 += v * v;
    }
    atomicAdd(&sums[col], s);
    atomicAdd(&sumsq[col], s2);
}

__global__ void bn_finalize(const float* __restrict__ sums, const float* __restrict__ sumsq,
                            float n, const float* __restrict__ gamma,
                            const float* __restrict__ beta,
                            float* __restrict__ scale, float* __restrict__ bias) {
    int c = threadIdx.x;
    float m = sums[c] / n;
    float var = sumsq[c] / n - m * m;
    float sc = gamma[c] * rsqrtf(var + BN_EPS);
    scale[c] = sc;
    bias[c]  = beta[c] - m * sc;
}

template<bool TANH>
__global__ void bn_apply(const float* __restrict__ X, const float* __restrict__ scale,
                         const float* __restrict__ bias, float* __restrict__ Y, int n4) {
    int i = blockIdx.x * blockDim.x + threadIdx.x;
    if (i >= n4) return;
    float4 x = ((const float4*)X)[i];
    int c = (i & 63) * 4;                    // row stride = 64 float4
    float4 y;
    y.x = x.x * scale[c + 0] + bias[c + 0];
    y.y = x.y * scale[c + 1] + bias[c + 1];
    y.z = x.z * scale[c + 2] + bias[c + 2];
    y.w = x.w * scale[c + 3] + bias[c + 3];
    if (TANH) { y.x = tanhf(y.x); y.y = tanhf(y.y); y.z = tanhf(y.z); y.w = tanhf(y.w); }
    ((float4*)Y)[i] = y;
}

// ---------------- hr = h (x) normalize(p)  (quaternion, per 64-slot) ----------------
__global__ void hr_quat(const int* __restrict__ e1, const int* __restrict__ ridx,
                        const float* __restrict__ X, const float* __restrict__ R,
                        float* __restrict__ hr) {
    int b = blockIdx.x, t = threadIdx.x;     // 512 blocks x 64 threads
    const float* h = X + (size_t)e1[b] * EMB;
    const float* p = R + (size_t)ridx[b] * EMB;
    float pr = p[t], pi = p[64 + t], pj = p[128 + t], pk = p[192 + t];
    float inv = 1.f / sqrtf(pr * pr + pi * pi + pj * pj + pk * pk);
    pr *= inv; pi *= inv; pj *= inv; pk *= inv;
    float hrr = h[t], hi = h[64 + t], hj = h[128 + t], hk = h[192 + t];
    float* o = hr + (size_t)b * EMB;
    o[t]       = hrr * pr - hi * pi - hj * pj - hk * pk;
    o[64 + t]  = hi * pr + hrr * pi - hk * pj + hj * pk;
    o[128 + t] = hj * pr + hk * pi + hrr * pj - hi * pk;
    o[192 + t] = hk * pr - hj * pi + hi * pj + hrr * pk;
}

// ---------------- driver ----------------
extern "C" void kernel_launch(void* const* d_in, const int* in_sizes, int n_in,
                              void* d_out, int out_size) {
    const int*   e1     = (const int*)  d_in[0];
    const int*   ridx   = (const int*)  d_in[1];
    const float* emb    = (const float*)d_in[2];
    const float* gcn1_w = (const float*)d_in[3];
    const float* gcn2_w = (const float*)d_in[4];
    const float* gcn1_g = (const float*)d_in[5];
    const float* gcn1_b = (const float*)d_in[6];
    const float* gcn2_g = (const float*)d_in[7];
    const float* gcn2_b = (const float*)d_in[8];
    const float* lin    = (const float*)d_in[9];
    const float* bns_g  = (const float*)d_in[10];
    const float* bns_b  = (const float*)d_in[11];
    const int*   adj_r  = (const int*)  d_in[12];
    const int*   adj_c  = (const int*)  d_in[13];
    const float* adj_v  = (const float*)d_in[14];
    const int*   adjr_r = (const int*)  d_in[15];
    const int*   adjr_c = (const int*)  d_in[16];
    const float* adjr_v = (const float*)d_in[17];
    float* out = (float*)d_out;

    float *XRa, *XRb, *S, *XRrf, *Xef, *hr, *hrbn, *sums, *sumsq, *scale, *bias;
    float *HG1T, *HG2T, *HeT, *HrT;
    cudaGetSymbolAddress((void**)&XRa,   g_XRa);
    cudaGetSymbolAddress((void**)&XRb,   g_XRb);
    cudaGetSymbolAddress((void**)&S,     g_S);
    cudaGetSymbolAddress((void**)&XRrf,  g_XRrf);
    cudaGetSymbolAddress((void**)&Xef,   g_Xef);
    cudaGetSymbolAddress((void**)&hr,    g_hr);
    cudaGetSymbolAddress((void**)&hrbn,  g_hrbn);
    cudaGetSymbolAddress((void**)&sums,  g_sums);
    cudaGetSymbolAddress((void**)&sumsq, g_sumsq);
    cudaGetSymbolAddress((void**)&scale, g_scale);
    cudaGetSymbolAddress((void**)&bias,  g_bias);
    cudaGetSymbolAddress((void**)&HG1T,  g_HG1T);
    cudaGetSymbolAddress((void**)&HG2T,  g_HG2T);
    cudaGetSymbolAddress((void**)&HeT,   g_HeT);
    cudaGetSymbolAddress((void**)&HrT,   g_HrT);

    auto bn_prep = [&](const float* X, int rows, const float* gamma, const float* beta) {
        cudaMemsetAsync(sums, 0, EMB * sizeof(float));
        cudaMemsetAsync(sumsq, 0, EMB * sizeof(float));
        int grid = rows > 4096 ? 512 : 8;
        bn_stats<<<grid, 256>>>(X, rows, sums, sumsq);
        bn_finalize<<<1, 256>>>(sums, sumsq, (float)rows, gamma, beta, scale, bias);
    };

    auto score = [&](int s, const float* X, const float* R) {
        hr_quat<<<BATCH, 64>>>(e1, ridx, X, R, hr);
        bn_prep(hr, BATCH, bns_g + s * EMB, bns_b + s * EMB);
        int n4 = BATCH * EMB / 4;
        bn_apply<false><<<(n4 + 255) / 256, 256>>>(hr, scale, bias, hrbn, n4);
        dim3 g((N_ENTS + 127) / 128, (BATCH + 127) / 128);
        gemm_tf32x3<2, 1><<<g, 256>>>(hrbn, X, nullptr, nullptr,
                                      out + (size_t)s * BATCH * N_ENTS,
                                      BATCH, N_ENTS);
    };

    auto q4gnn = [&](const float* Ain, int nrows, const int* er, const int* ec,
                     const float* ev, const float* HT, const float* gamma,
                     const float* beta, float* Aout) {
        dim3 g(2, (nrows + 127) / 128);
        gemm_tf32x3<0, 1><<<g, 256>>>(Ain, HT, nullptr, nullptr, S, nrows, EMB);
        cudaMemsetAsync(Aout, 0, (size_t)nrows * EMB * sizeof(float));
        segsum<<<NEDGE / 8, 256>>>(er, ec, ev, S, Aout, NEDGE);
        bn_prep(Aout, nrows, gamma, beta);
        int n4 = nrows * EMB / 4;
        bn_apply<true><<<(n4 + 255) / 256, 256>>>(Aout, scale, bias, Aout, n4);
    };

    // score 0 on raw embeddings (X = emb[:50000], R = emb[50000:] contiguous)
    score(0, emb, emb + (size_t)N_ENTS * EMB);

    const float* XRcur = emb;
    float* XRbufs[2] = {XRa, XRb};
    for (int l = 0; l < 2; l++) {
        build_gcn_ht<<<256, 256>>>(gcn2_w + (size_t)l * 64 * 256, HG2T);
        build_gcn_ht<<<256, 256>>>(gcn1_w + (size_t)l * 64 * 256, HG1T);
        build_lin_ht<<<256, 256>>>(lin + (size_t)l * 128 * 256, HeT, HrT);

        q4gnn(XRcur, NTOT,   adjr_r, adjr_c, adjr_v, HG2T,
              gcn2_g + l * EMB, gcn2_b + l * EMB, XRrf);
        q4gnn(XRcur, N_ENTS, adj_r,  adj_c,  adj_v,  HG1T,
              gcn1_g + l * EMB, gcn1_b + l * EMB, Xef);

        // fused lin: Xnext = Xef*HeT^T + XRrf*HrT^T  (single kernel, K=512)
        float* XRnext = XRbufs[l];
        dim3 g(2, (N_ENTS + 127) / 128);
        gemm_tf32x3<0, 2><<<g, 256>>>(Xef, HeT, XRrf, HrT, XRnext, N_ENTS, EMB);
        cudaMemcpyAsync(XRnext + (size_t)N_ENTS * EMB, XRrf + (size_t)N_ENTS * EMB,
                        (size_t)N_RELS * EMB * sizeof(float), cudaMemcpyDeviceToDevice);

        score(l + 1, XRnext, XRnext + (size_t)N_ENTS * EMB);
        XRcur = XRnext;
    }
}